// round 3
// baseline (speedup 1.0000x reference)
#include <cuda_runtime.h>
#include <cuda_bf16.h>
#include <math.h>

// ---------------------------------------------------------------------------
// Problem constants
// ---------------------------------------------------------------------------
#define BB   8        // batch
#define PP   1024     // points
#define FIN  64
#define MM   160      // multiplicity
#define DOUT 5120
#define TOTAL_K 2560
#define MID  32
#define RWID 10240    // M*FIN

// ---------------------------------------------------------------------------
// Scratch (static device globals; no allocations allowed)
// ---------------------------------------------------------------------------
__device__ float g_R   [3*4*BB*RWID];                 // radial outputs  (3.75 MB)
__device__ float g_kern[(size_t)3*BB*FIN*TOTAL_K];    // kernels         (15.7 MB)
__device__ float g_qkv [(size_t)3*BB*PP*TOTAL_K];     // q/k/v           (252 MB)
__device__ float g_e   [(size_t)BB*PP*PP];            // attn scores (1 degree, 33.5 MB)
__device__ float g_z   [(size_t)BB*PP*TOTAL_K];       // attn output     (84 MB)
__device__ float g_y   [(size_t)BB*PP*DOUT];          // post-Wl1        (168 MB)

// ---------------------------------------------------------------------------
// Kernel 1: stacked radial MLPs.  One block per (t,g,b) = 96 blocks.
//   h1 = relu(LN(r*W1+b1)); h2 = relu(LN(h1@W2+b2)); R = h2@W3 + b3
// ---------------------------------------------------------------------------
__global__ void radial_kernel(const float* __restrict__ r,
                              const float* __restrict__ W1, const float* __restrict__ b1,
                              const float* __restrict__ g1, const float* __restrict__ be1,
                              const float* __restrict__ W2, const float* __restrict__ b2,
                              const float* __restrict__ g2, const float* __restrict__ be2,
                              const float* __restrict__ W3, const float* __restrict__ b3,
                              float* __restrict__ R)
{
    int id  = blockIdx.x;     // tg*8 + b
    int b   = id & 7;
    int tg  = id >> 3;        // t*4+g
    int tid = threadIdx.x;
    float rb = r[b];          // r is [B,1]

    __shared__ float h1[32], h2[32];

    if (tid < 32) {
        float v = rb * W1[tg*32 + tid] + b1[tg*32 + tid];
        float mu = v;
        #pragma unroll
        for (int o = 16; o; o >>= 1) mu += __shfl_xor_sync(0xffffffffu, mu, o);
        mu *= (1.f/32.f);
        float d = v - mu;
        float var = d*d;
        #pragma unroll
        for (int o = 16; o; o >>= 1) var += __shfl_xor_sync(0xffffffffu, var, o);
        var *= (1.f/32.f);
        float x = d * rsqrtf(var + 1e-5f) * g1[tg*32 + tid] + be1[tg*32 + tid];
        h1[tid] = fmaxf(x, 0.f);
    }
    __syncthreads();

    if (tid < 32) {
        float acc = b2[tg*32 + tid];
        const float* w = W2 + ((size_t)tg*32 + tid) * 32;
        #pragma unroll
        for (int i = 0; i < 32; i++) acc += h1[i] * w[i];
        float mu = acc;
        #pragma unroll
        for (int o = 16; o; o >>= 1) mu += __shfl_xor_sync(0xffffffffu, mu, o);
        mu *= (1.f/32.f);
        float d = acc - mu;
        float var = d*d;
        #pragma unroll
        for (int o = 16; o; o >>= 1) var += __shfl_xor_sync(0xffffffffu, var, o);
        var *= (1.f/32.f);
        float x = d * rsqrtf(var + 1e-5f) * g2[tg*32 + tid] + be2[tg*32 + tid];
        h2[tid] = fmaxf(x, 0.f);
    }
    __syncthreads();

    for (int o = tid; o < RWID; o += blockDim.x) {
        float acc = b3[(size_t)tg*RWID + o];
        const float* w = W3 + ((size_t)tg*RWID + o) * 32;
        #pragma unroll
        for (int i = 0; i < 32; i++) acc += h2[i] * w[i];
        R[(size_t)id*RWID + o] = acc;
    }
}

// ---------------------------------------------------------------------------
// Kernel 2: build kern[t,b,i,ktot] implementing the "faithful .view":
//   flat = i*(M*dout)+kg ; mo = flat/(dout*64) ; j = (flat/64)%dout ; mi = flat%64
//   kern = R[t,g,b, mo*64+mi] * basis_g[b, j]
// ---------------------------------------------------------------------------
__global__ void build_kern(const float* __restrict__ R,
                           const float* __restrict__ bas0, const float* __restrict__ bas1,
                           const float* __restrict__ bas2, const float* __restrict__ bas3,
                           float* __restrict__ kern)
{
    long idx = (long)blockIdx.x * blockDim.x + threadIdx.x;
    const long total = 3L * BB * FIN * TOTAL_K;
    if (idx >= total) return;

    int ktot = (int)(idx % TOTAL_K);
    long rem = idx / TOTAL_K;
    int i = (int)(rem % FIN);
    rem /= FIN;
    int b = (int)(rem % BB);
    int t = (int)(rem / BB);

    int g, k0, dout;
    const float* bas;
    if      (ktot < 160)  { g = 0; k0 = 0;    dout = 1; bas = bas0; }
    else if (ktot < 640)  { g = 1; k0 = 160;  dout = 3; bas = bas1; }
    else if (ktot < 1440) { g = 2; k0 = 640;  dout = 5; bas = bas2; }
    else                  { g = 3; k0 = 1440; dout = 7; bas = bas3; }

    int kg  = ktot - k0;
    int lin = i * (MM * dout) + kg;
    int mo  = lin / (dout * FIN);
    int j   = (lin / FIN) % dout;
    int mi  = lin % FIN;

    float v = R[((size_t)((t*4 + g)*BB + b))*RWID + mo*FIN + mi] * bas[b*dout + j];
    kern[idx] = v;
}

// ---------------------------------------------------------------------------
// Generic batched SGEMM, 128x128x8 tile, 8x8 per thread, 256 threads.
//   TRANS_B = 0 : C[m,n] += A[m,k] * B[k,n]     (B is [K,N], ldb)
//   TRANS_B = 1 : C[m,n] += A[m,k] * B[n,k]     (B is [N,K], ldb)
//   CHECK   = 0 : all tiles full, lda/ldb/ldc %4==0, K%8==0 -> float4 fast path
// C = (acc ? C : 0) + alpha * (A·B) + (bias ? bias[n] : 0)
// ---------------------------------------------------------------------------
template<int TRANS_B, int CHECK>
__global__ __launch_bounds__(256)
void sgemm(const float* __restrict__ A, const float* __restrict__ B,
           float* __restrict__ C,
           int M, int N, int K, int lda, int ldb, int ldc,
           long sA, long sB, long sC,
           float alpha, const float* __restrict__ bias, int acc)
{
    const int BM = 128, BN = 128, BK = 8;
    __shared__ __align__(16) float As[BK][BM];
    __shared__ __align__(16) float Bs[BK][BN];

    A += (long)blockIdx.z * sA;
    B += (long)blockIdx.z * sB;
    C += (long)blockIdx.z * sC;

    int m0 = blockIdx.y * BM;
    int n0 = blockIdx.x * BN;
    int tid = threadIdx.x;
    int tr = tid >> 4;        // 0..15
    int tc = tid & 15;        // 0..15

    float accr[8][8];
    #pragma unroll
    for (int i = 0; i < 8; i++)
        #pragma unroll
        for (int j = 0; j < 8; j++) accr[i][j] = 0.f;

    int arow  = tid >> 1;          // 0..127
    int acol4 = (tid & 1) * 4;     // 0 or 4
    int bnrow = tid >> 1;          // NT: 0..127
    int bncol = (tid & 1) * 4;
    int bkrow = tid >> 5;          // NN: 0..7
    int bkcol = (tid & 31) * 4;    // 0..124

    for (int k0 = 0; k0 < K; k0 += BK) {
        // ---- A tile (BM x BK), stored transposed ----
        if (CHECK) {
            #pragma unroll
            for (int j = 0; j < 4; j++) {
                int m = m0 + arow, k = k0 + acol4 + j;
                As[acol4 + j][arow] = (m < M && k < K) ? A[(long)m*lda + k] : 0.f;
            }
        } else {
            float4 av = *(const float4*)&A[(long)(m0 + arow)*lda + k0 + acol4];
            As[acol4 + 0][arow] = av.x;
            As[acol4 + 1][arow] = av.y;
            As[acol4 + 2][arow] = av.z;
            As[acol4 + 3][arow] = av.w;
        }
        // ---- B tile ----
        if (TRANS_B) {
            if (CHECK) {
                #pragma unroll
                for (int j = 0; j < 4; j++) {
                    int n = n0 + bnrow, k = k0 + bncol + j;
                    Bs[bncol + j][bnrow] = (n < N && k < K) ? B[(long)n*ldb + k] : 0.f;
                }
            } else {
                float4 bv = *(const float4*)&B[(long)(n0 + bnrow)*ldb + k0 + bncol];
                Bs[bncol + 0][bnrow] = bv.x;
                Bs[bncol + 1][bnrow] = bv.y;
                Bs[bncol + 2][bnrow] = bv.z;
                Bs[bncol + 3][bnrow] = bv.w;
            }
        } else {
            if (CHECK) {
                #pragma unroll
                for (int j = 0; j < 4; j++) {
                    int k = k0 + bkrow, n = n0 + bkcol + j;
                    Bs[bkrow][bkcol + j] = (k < K && n < N) ? B[(long)k*ldb + n] : 0.f;
                }
            } else {
                *(float4*)&Bs[bkrow][bkcol] =
                    *(const float4*)&B[(long)(k0 + bkrow)*ldb + n0 + bkcol];
            }
        }
        __syncthreads();

        #pragma unroll
        for (int kk = 0; kk < BK; kk++) {
            float a[8], bv[8];
            *(float4*)&a[0]  = *(const float4*)&As[kk][tr*8];
            *(float4*)&a[4]  = *(const float4*)&As[kk][tr*8 + 4];
            *(float4*)&bv[0] = *(const float4*)&Bs[kk][tc*8];
            *(float4*)&bv[4] = *(const float4*)&Bs[kk][tc*8 + 4];
            #pragma unroll
            for (int i = 0; i < 8; i++)
                #pragma unroll
                for (int j = 0; j < 8; j++)
                    accr[i][j] += a[i] * bv[j];
        }
        __syncthreads();
    }

    // ---- epilogue ----
    if (CHECK) {
        #pragma unroll
        for (int i = 0; i < 8; i++) {
            int m = m0 + tr*8 + i;
            if (m >= M) continue;
            #pragma unroll
            for (int j = 0; j < 8; j++) {
                int n = n0 + tc*8 + j;
                if (n >= N) continue;
                float v = accr[i][j] * alpha;
                if (bias) v += bias[n];
                if (acc)  v += C[(long)m*ldc + n];
                C[(long)m*ldc + n] = v;
            }
        }
    } else {
        #pragma unroll
        for (int i = 0; i < 8; i++) {
            long row = (long)(m0 + tr*8 + i) * ldc + n0 + tc*8;
            #pragma unroll
            for (int jj = 0; jj < 2; jj++) {
                float4 v;
                v.x = accr[i][jj*4 + 0] * alpha;
                v.y = accr[i][jj*4 + 1] * alpha;
                v.z = accr[i][jj*4 + 2] * alpha;
                v.w = accr[i][jj*4 + 3] * alpha;
                if (bias) {
                    const float4 bb4 = *(const float4*)&bias[n0 + tc*8 + jj*4];
                    v.x += bb4.x; v.y += bb4.y; v.z += bb4.z; v.w += bb4.w;
                }
                if (acc) {
                    const float4 c4 = *(const float4*)&C[row + jj*4];
                    v.x += c4.x; v.y += c4.y; v.z += c4.z; v.w += c4.w;
                }
                *(float4*)&C[row + jj*4] = v;
            }
        }
    }
}

// ---------------------------------------------------------------------------
// Kernel: softmax over axis p (rows) for each column q, in place.
// e layout: [b][p][q] with p-stride 1024. Consecutive threads own
// consecutive q -> coalesced. Online max/sum, then one write pass.
// ---------------------------------------------------------------------------
__global__ void col_softmax(float* __restrict__ e)
{
    int b = blockIdx.y;
    int q = blockIdx.x * blockDim.x + threadIdx.x;   // 0..1023
    float* base = e + (size_t)b * PP * PP + q;

    float m = -INFINITY, s = 0.f;
    for (int p = 0; p < PP; p++) {
        float v  = base[(size_t)p * PP];
        float nm = fmaxf(m, v);
        s = s * __expf(m - nm) + __expf(v - nm);
        m = nm;
    }
    float inv = 1.f / s;
    for (int p = 0; p < PP; p++) {
        size_t off = (size_t)p * PP;
        base[off] = __expf(base[off] - m) * inv;
    }
}

// ---------------------------------------------------------------------------
// Kernel: row LayerNorm over 5120 + ReLU, in place. One block per row.
// Values cached in registers (20 per thread) to avoid rereads.
// ---------------------------------------------------------------------------
__global__ __launch_bounds__(256)
void ln_relu(float* __restrict__ y, const float* __restrict__ gg,
             const float* __restrict__ bb)
{
    long row = blockIdx.x;
    float* p = y + row * DOUT;
    int tid = threadIdx.x;

    float v[20];
    float s = 0.f;
    #pragma unroll
    for (int j = 0; j < 20; j++) { v[j] = p[tid + j*256]; s += v[j]; }

    __shared__ float red[256];
    red[tid] = s; __syncthreads();
    #pragma unroll
    for (int st = 128; st; st >>= 1) {
        if (tid < st) red[tid] += red[tid + st];
        __syncthreads();
    }
    float mu = red[0] * (1.f / DOUT);
    __syncthreads();

    float qs = 0.f;
    #pragma unroll
    for (int j = 0; j < 20; j++) { float d = v[j] - mu; qs += d*d; }
    red[tid] = qs; __syncthreads();
    #pragma unroll
    for (int st = 128; st; st >>= 1) {
        if (tid < st) red[tid] += red[tid + st];
        __syncthreads();
    }
    float is = rsqrtf(red[0] * (1.f / DOUT) + 1e-5f);

    #pragma unroll
    for (int j = 0; j < 20; j++) {
        int o = tid + j*256;
        float x = (v[j] - mu) * is * gg[o] + bb[o];
        p[o] = fmaxf(x, 0.f);
    }
}

// ---------------------------------------------------------------------------
// Launch
// ---------------------------------------------------------------------------
extern "C" void kernel_launch(void* const* d_in, const int* in_sizes, int n_in,
                              void* d_out, int out_size)
{
    const float* f     = (const float*)d_in[0];   // [8,1024,64]
    const float* r     = (const float*)d_in[1];   // [8,1]
    const float* bas0  = (const float*)d_in[2];
    const float* bas1  = (const float*)d_in[3];
    const float* bas2  = (const float*)d_in[4];
    const float* bas3  = (const float*)d_in[5];
    const float* W1    = (const float*)d_in[6];
    const float* b1    = (const float*)d_in[7];
    const float* g1    = (const float*)d_in[8];
    const float* be1   = (const float*)d_in[9];
    const float* W2    = (const float*)d_in[10];
    const float* b2    = (const float*)d_in[11];
    const float* g2    = (const float*)d_in[12];
    const float* be2   = (const float*)d_in[13];
    const float* W3    = (const float*)d_in[14];
    const float* b3    = (const float*)d_in[15];
    const float* trans = (const float*)d_in[16];  // [8,64,5120]
    const float* Wl1   = (const float*)d_in[17];  // [5120,2560]
    const float* bl1   = (const float*)d_in[18];
    const float* ln_g  = (const float*)d_in[19];
    const float* ln_b  = (const float*)d_in[20];
    const float* Wl2   = (const float*)d_in[21];  // [5120,5120]
    const float* bl2   = (const float*)d_in[22];
    float* out = (float*)d_out;

    float *R, *kern, *qkv, *e, *z, *y;
    cudaGetSymbolAddress((void**)&R,    g_R);
    cudaGetSymbolAddress((void**)&kern, g_kern);
    cudaGetSymbolAddress((void**)&qkv,  g_qkv);
    cudaGetSymbolAddress((void**)&e,    g_e);
    cudaGetSymbolAddress((void**)&z,    g_z);
    cudaGetSymbolAddress((void**)&y,    g_y);

    // 1) radial MLPs -> R
    radial_kernel<<<96, 256>>>(r, W1, b1, g1, be1, W2, b2, g2, be2, W3, b3, R);

    // 2) kernels
    {
        long total = 3L * BB * FIN * TOTAL_K;
        build_kern<<<(unsigned)((total + 255) / 256), 256>>>(R, bas0, bas1, bas2, bas3, kern);
    }

    // 3) qkv[t,b] = features[b] @ kern[t,b]   (M=1024,N=2560,K=64), 3 batched launches
    for (int t = 0; t < 3; t++) {
        dim3 grid(TOTAL_K/128, PP/128, BB);
        sgemm<0,0><<<grid, 256>>>(f,
                                  kern + (long)t*BB*FIN*TOTAL_K,
                                  qkv  + (long)t*BB*PP*TOTAL_K,
                                  PP, TOTAL_K, FIN, FIN, TOTAL_K, TOTAL_K,
                                  (long)PP*FIN, (long)FIN*TOTAL_K, (long)PP*TOTAL_K,
                                  1.f, nullptr, 0);
    }

    const int K0[4] = {0, 160, 640, 1440};
    const int KG[4] = {160, 480, 800, 1120};

    // 4-6) per-degree attention, reusing one score buffer e[8,1024,1024]
    for (int g = 0; g < 4; g++) {
        // scores: e[b] = scale * Q_seg @ K_seg^T  (M=N=1024, K=KG[g], full tiles)
        {
            dim3 grid(PP/128, PP/128, BB);
            float scale = 1.0f / sqrtf((float)KG[g]);
            sgemm<1,0><<<grid, 256>>>(qkv + 2L*BB*PP*TOTAL_K + K0[g],
                                      qkv + 1L*BB*PP*TOTAL_K + K0[g],
                                      e,
                                      PP, PP, KG[g], TOTAL_K, TOTAL_K, PP,
                                      (long)PP*TOTAL_K, (long)PP*TOTAL_K, (long)PP*PP,
                                      scale, nullptr, 0);
        }
        // softmax over p for each column q
        col_softmax<<<dim3(PP/256, BB), 256>>>(e);
        // z segment = alpha @ V_seg  (M=1024, N=KG[g], K=1024) — partial N tiles
        {
            dim3 grid((KG[g] + 127)/128, PP/128, BB);
            sgemm<0,1><<<grid, 256>>>(e,
                                      qkv + K0[g],               // t=0 (v)
                                      z   + K0[g],
                                      PP, KG[g], PP, PP, TOTAL_K, TOTAL_K,
                                      (long)PP*PP, (long)PP*TOTAL_K, (long)PP*TOTAL_K,
                                      1.f, nullptr, 0);
        }
    }

    // 7) y = z @ Wl1^T + bl1   (M=8192, N=5120, K=2560)
    {
        dim3 grid(DOUT/128, (BB*PP)/128, 1);
        sgemm<1,0><<<grid, 256>>>(z, Wl1, y,
                                  BB*PP, DOUT, TOTAL_K, TOTAL_K, TOTAL_K, DOUT,
                                  0, 0, 0, 1.f, bl1, 0);
    }

    // 8) LayerNorm + ReLU in place on y
    ln_relu<<<BB*PP, 256>>>(y, ln_g, ln_b);

    // 9) out = features @ transform + bl2   (per-b, M=1024, N=5120, K=64)
    {
        dim3 grid(DOUT/128, PP/128, BB);
        sgemm<0,0><<<grid, 256>>>(f, trans, out,
                                  PP, DOUT, FIN, FIN, DOUT, DOUT,
                                  (long)PP*FIN, (long)FIN*DOUT, (long)PP*DOUT,
                                  1.f, bl2, 0);
    }

    // 10) out += y @ Wl2^T   (M=8192, N=5120, K=5120)
    {
        dim3 grid(DOUT/128, (BB*PP)/128, 1);
        sgemm<1,0><<<grid, 256>>>(y, Wl2, out,
                                  BB*PP, DOUT, DOUT, DOUT, DOUT, DOUT,
                                  0, 0, 0, 1.f, nullptr, 1);
    }
}

// round 6
// speedup vs baseline: 1.0702x; 1.0702x over previous
#include <cuda_runtime.h>
#include <cuda_bf16.h>
#include <math.h>

// ---------------------------------------------------------------------------
// Problem constants
// ---------------------------------------------------------------------------
#define BB   8        // batch
#define PP   1024     // points
#define FIN  64
#define MM   160      // multiplicity
#define DOUT 5120
#define TOTAL_K 2560
#define MID  32
#define RWID 10240    // M*FIN

// ---------------------------------------------------------------------------
// Scratch (static device globals; no allocations allowed)
// ---------------------------------------------------------------------------
__device__ float g_R   [3*4*BB*RWID];                 // radial outputs  (3.75 MB)
__device__ float g_kern[(size_t)3*BB*FIN*TOTAL_K];    // kernels         (15.7 MB)
__device__ float g_qkv [(size_t)3*BB*PP*TOTAL_K];     // q/k/v           (252 MB)
__device__ float g_e   [(size_t)BB*PP*PP];            // attn scores (1 degree, 33.5 MB)
__device__ float g_z   [(size_t)BB*PP*TOTAL_K];       // attn output     (84 MB)
__device__ float g_y   [(size_t)BB*PP*DOUT];          // post-Wl1        (168 MB)

// ---------------------------------------------------------------------------
// Kernel 1: stacked radial MLPs.  One block per (t,g,b) = 96 blocks.
// ---------------------------------------------------------------------------
__global__ void radial_kernel(const float* __restrict__ r,
                              const float* __restrict__ W1, const float* __restrict__ b1,
                              const float* __restrict__ g1, const float* __restrict__ be1,
                              const float* __restrict__ W2, const float* __restrict__ b2,
                              const float* __restrict__ g2, const float* __restrict__ be2,
                              const float* __restrict__ W3, const float* __restrict__ b3,
                              float* __restrict__ R)
{
    int id  = blockIdx.x;     // tg*8 + b
    int b   = id & 7;
    int tg  = id >> 3;        // t*4+g
    int tid = threadIdx.x;
    float rb = r[b];          // r is [B,1]

    __shared__ float h1[32], h2[32];

    if (tid < 32) {
        float v = rb * W1[tg*32 + tid] + b1[tg*32 + tid];
        float mu = v;
        #pragma unroll
        for (int o = 16; o; o >>= 1) mu += __shfl_xor_sync(0xffffffffu, mu, o);
        mu *= (1.f/32.f);
        float d = v - mu;
        float var = d*d;
        #pragma unroll
        for (int o = 16; o; o >>= 1) var += __shfl_xor_sync(0xffffffffu, var, o);
        var *= (1.f/32.f);
        float x = d * rsqrtf(var + 1e-5f) * g1[tg*32 + tid] + be1[tg*32 + tid];
        h1[tid] = fmaxf(x, 0.f);
    }
    __syncthreads();

    if (tid < 32) {
        float acc = b2[tg*32 + tid];
        const float* w = W2 + ((size_t)tg*32 + tid) * 32;
        #pragma unroll
        for (int i = 0; i < 32; i++) acc += h1[i] * w[i];
        float mu = acc;
        #pragma unroll
        for (int o = 16; o; o >>= 1) mu += __shfl_xor_sync(0xffffffffu, mu, o);
        mu *= (1.f/32.f);
        float d = acc - mu;
        float var = d*d;
        #pragma unroll
        for (int o = 16; o; o >>= 1) var += __shfl_xor_sync(0xffffffffu, var, o);
        var *= (1.f/32.f);
        float x = d * rsqrtf(var + 1e-5f) * g2[tg*32 + tid] + be2[tg*32 + tid];
        h2[tid] = fmaxf(x, 0.f);
    }
    __syncthreads();

    for (int o = tid; o < RWID; o += blockDim.x) {
        float acc = b3[(size_t)tg*RWID + o];
        const float* w = W3 + ((size_t)tg*RWID + o) * 32;
        #pragma unroll
        for (int i = 0; i < 32; i++) acc += h2[i] * w[i];
        R[(size_t)id*RWID + o] = acc;
    }
}

// ---------------------------------------------------------------------------
// Kernel 2: build kern[t,b,i,ktot] implementing the "faithful .view"
// ---------------------------------------------------------------------------
__global__ void build_kern(const float* __restrict__ R,
                           const float* __restrict__ bas0, const float* __restrict__ bas1,
                           const float* __restrict__ bas2, const float* __restrict__ bas3,
                           float* __restrict__ kern)
{
    long idx = (long)blockIdx.x * blockDim.x + threadIdx.x;
    const long total = 3L * BB * FIN * TOTAL_K;
    if (idx >= total) return;

    int ktot = (int)(idx % TOTAL_K);
    long rem = idx / TOTAL_K;
    int i = (int)(rem % FIN);
    rem /= FIN;
    int b = (int)(rem % BB);
    int t = (int)(rem / BB);

    int g, k0, dout;
    const float* bas;
    if      (ktot < 160)  { g = 0; k0 = 0;    dout = 1; bas = bas0; }
    else if (ktot < 640)  { g = 1; k0 = 160;  dout = 3; bas = bas1; }
    else if (ktot < 1440) { g = 2; k0 = 640;  dout = 5; bas = bas2; }
    else                  { g = 3; k0 = 1440; dout = 7; bas = bas3; }

    int kg  = ktot - k0;
    int lin = i * (MM * dout) + kg;
    int mo  = lin / (dout * FIN);
    int j   = (lin / FIN) % dout;
    int mi  = lin % FIN;

    float v = R[((size_t)((t*4 + g)*BB + b))*RWID + mo*FIN + mi] * bas[b*dout + j];
    kern[idx] = v;
}

// ---------------------------------------------------------------------------
// 3xTF32 tensor-core GEMM (near-fp32 accuracy).
// 128x128x16 tile, 256 threads (8 warps, 2Mx4N), warp = 64x32 via 4x4
// m16n8k8 fragments.  Each operand split x = hi + lo (hi=tf32(x),
// lo=tf32(x-hi)); accumulate hi*hi + hi*lo + lo*hi in fp32.
//   TRANS_B=0 : C = A[m,k] * B[k,n] ;  TRANS_B=1 : C = A[m,k] * B[n,k]
//   CHECK=0   : full tiles, K%16==0, 16B-aligned rows -> float4 path
// C = (acc?C:0) + alpha*(A.B) + (bias?bias[n]:0)
// ---------------------------------------------------------------------------
#define KP 20   // padded smem row stride

__device__ __forceinline__ unsigned f2tf(float x) {
    unsigned r;
    asm("cvt.rna.tf32.f32 %0, %1;" : "=r"(r) : "f"(x));
    return r;
}

__device__ __forceinline__ void split_tf32(float x, unsigned& hi, unsigned& lo) {
    hi = f2tf(x);
    float hif = __uint_as_float(hi);
    lo = f2tf(x - hif);
}

__device__ __forceinline__ void mma_tf32(float c[4], const unsigned a[4],
                                         const unsigned b[2]) {
    asm volatile(
        "mma.sync.aligned.m16n8k8.row.col.f32.tf32.tf32.f32 "
        "{%0,%1,%2,%3}, {%4,%5,%6,%7}, {%8,%9}, {%0,%1,%2,%3};"
        : "+f"(c[0]), "+f"(c[1]), "+f"(c[2]), "+f"(c[3])
        : "r"(a[0]), "r"(a[1]), "r"(a[2]), "r"(a[3]), "r"(b[0]), "r"(b[1]));
}

template<int TRANS_B, int CHECK>
__global__ __launch_bounds__(256)
void tmma(const float* __restrict__ A, const float* __restrict__ B,
          float* __restrict__ C,
          int M, int N, int K, int lda, int ldb, int ldc,
          long sA, long sB, long sC,
          float alpha, const float* __restrict__ bias, int acc)
{
    __shared__ __align__(16) unsigned AsH[128*KP];
    __shared__ __align__(16) unsigned AsL[128*KP];
    __shared__ __align__(16) unsigned BsH[128*KP];
    __shared__ __align__(16) unsigned BsL[128*KP];

    A += (long)blockIdx.z * sA;
    B += (long)blockIdx.z * sB;
    C += (long)blockIdx.z * sC;

    const int m0 = blockIdx.y * 128;
    const int n0 = blockIdx.x * 128;
    const int tid  = threadIdx.x;
    const int lane = tid & 31;
    const int warp = tid >> 5;
    const int wm = warp & 1;        // 0..1  (64-row group)
    const int wn = warp >> 1;       // 0..3  (32-col group)
    const int g  = lane >> 2;       // 0..7
    const int t  = lane & 3;        // 0..3

    float c[4][4][4];
    #pragma unroll
    for (int i = 0; i < 4; i++)
        #pragma unroll
        for (int j = 0; j < 4; j++)
            #pragma unroll
            for (int k = 0; k < 4; k++) c[i][j][k] = 0.f;

    for (int k0 = 0; k0 < K; k0 += 16) {
        // ---- A tile: 128 x 16 ----
        #pragma unroll
        for (int j = 0; j < 2; j++) {
            int idx = tid + j*256;
            int m = idx >> 2, kq = idx & 3;
            float v[4];
            if (CHECK) {
                #pragma unroll
                for (int e = 0; e < 4; e++) {
                    int mm = m0 + m, kk = k0 + kq*4 + e;
                    v[e] = (mm < M && kk < K) ? A[(long)mm*lda + kk] : 0.f;
                }
            } else {
                float4 v4 = *(const float4*)&A[(long)(m0 + m)*lda + k0 + kq*4];
                v[0] = v4.x; v[1] = v4.y; v[2] = v4.z; v[3] = v4.w;
            }
            uint4 h, l;
            split_tf32(v[0], h.x, l.x); split_tf32(v[1], h.y, l.y);
            split_tf32(v[2], h.z, l.z); split_tf32(v[3], h.w, l.w);
            *(uint4*)&AsH[m*KP + kq*4] = h;
            *(uint4*)&AsL[m*KP + kq*4] = l;
        }
        // ---- B tile -> Bs[n][k] ----
        if (TRANS_B) {
            #pragma unroll
            for (int j = 0; j < 2; j++) {
                int idx = tid + j*256;
                int n = idx >> 2, kq = idx & 3;
                float v[4];
                if (CHECK) {
                    #pragma unroll
                    for (int e = 0; e < 4; e++) {
                        int nn = n0 + n, kk = k0 + kq*4 + e;
                        v[e] = (nn < N && kk < K) ? B[(long)nn*ldb + kk] : 0.f;
                    }
                } else {
                    float4 v4 = *(const float4*)&B[(long)(n0 + n)*ldb + k0 + kq*4];
                    v[0] = v4.x; v[1] = v4.y; v[2] = v4.z; v[3] = v4.w;
                }
                uint4 h, l;
                split_tf32(v[0], h.x, l.x); split_tf32(v[1], h.y, l.y);
                split_tf32(v[2], h.z, l.z); split_tf32(v[3], h.w, l.w);
                *(uint4*)&BsH[n*KP + kq*4] = h;
                *(uint4*)&BsL[n*KP + kq*4] = l;
            }
        } else {
            #pragma unroll
            for (int j = 0; j < 2; j++) {
                int idx = tid + j*256;
                int kr = idx >> 5, nq = idx & 31;   // kr 0..15, nq 0..31
                float v[4];
                if (CHECK) {
                    #pragma unroll
                    for (int e = 0; e < 4; e++) {
                        int nn = n0 + nq*4 + e, kk = k0 + kr;
                        v[e] = (nn < N && kk < K) ? B[(long)kk*ldb + nn] : 0.f;
                    }
                } else {
                    float4 v4 = *(const float4*)&B[(long)(k0 + kr)*ldb + n0 + nq*4];
                    v[0] = v4.x; v[1] = v4.y; v[2] = v4.z; v[3] = v4.w;
                }
                #pragma unroll
                for (int e = 0; e < 4; e++) {
                    unsigned h, l;
                    split_tf32(v[e], h, l);
                    BsH[(nq*4 + e)*KP + kr] = h;
                    BsL[(nq*4 + e)*KP + kr] = l;
                }
            }
        }
        __syncthreads();

        #pragma unroll
        for (int ks = 0; ks < 16; ks += 8) {
            unsigned afH[4][4], afL[4][4], bfH[4][2], bfL[4][2];
            #pragma unroll
            for (int mt = 0; mt < 4; mt++) {
                int am = wm*64 + mt*16;
                afH[mt][0] = AsH[(am + g    )*KP + ks + t    ];
                afH[mt][1] = AsH[(am + g + 8)*KP + ks + t    ];
                afH[mt][2] = AsH[(am + g    )*KP + ks + t + 4];
                afH[mt][3] = AsH[(am + g + 8)*KP + ks + t + 4];
                afL[mt][0] = AsL[(am + g    )*KP + ks + t    ];
                afL[mt][1] = AsL[(am + g + 8)*KP + ks + t    ];
                afL[mt][2] = AsL[(am + g    )*KP + ks + t + 4];
                afL[mt][3] = AsL[(am + g + 8)*KP + ks + t + 4];
            }
            #pragma unroll
            for (int nt = 0; nt < 4; nt++) {
                int bn = wn*32 + nt*8;
                bfH[nt][0] = BsH[(bn + g)*KP + ks + t    ];
                bfH[nt][1] = BsH[(bn + g)*KP + ks + t + 4];
                bfL[nt][0] = BsL[(bn + g)*KP + ks + t    ];
                bfL[nt][1] = BsL[(bn + g)*KP + ks + t + 4];
            }
            #pragma unroll
            for (int mt = 0; mt < 4; mt++)
                #pragma unroll
                for (int nt = 0; nt < 4; nt++) {
                    mma_tf32(c[mt][nt], afH[mt], bfL[nt]);
                    mma_tf32(c[mt][nt], afL[mt], bfH[nt]);
                    mma_tf32(c[mt][nt], afH[mt], bfH[nt]);
                }
        }
        __syncthreads();
    }

    // ---- epilogue ----
    #pragma unroll
    for (int mt = 0; mt < 4; mt++) {
        #pragma unroll
        for (int nt = 0; nt < 4; nt++) {
            int col = n0 + wn*32 + nt*8 + t*2;
            #pragma unroll
            for (int h = 0; h < 2; h++) {
                int row = m0 + wm*64 + mt*16 + g + h*8;
                float v0 = c[mt][nt][h*2 + 0] * alpha;
                float v1 = c[mt][nt][h*2 + 1] * alpha;
                if (CHECK) {
                    if (row < M) {
                        if (col < N) {
                            float w = v0;
                            if (bias) w += bias[col];
                            if (acc)  w += C[(long)row*ldc + col];
                            C[(long)row*ldc + col] = w;
                        }
                        if (col + 1 < N) {
                            float w = v1;
                            if (bias) w += bias[col + 1];
                            if (acc)  w += C[(long)row*ldc + col + 1];
                            C[(long)row*ldc + col + 1] = w;
                        }
                    }
                } else {
                    long off = (long)row*ldc + col;
                    if (bias) { v0 += bias[col]; v1 += bias[col + 1]; }
                    if (acc) {
                        float2 c2 = *(const float2*)&C[off];
                        v0 += c2.x; v1 += c2.y;
                    }
                    float2 o2; o2.x = v0; o2.y = v1;
                    *(float2*)&C[off] = o2;
                }
            }
        }
    }
}

// ---------------------------------------------------------------------------
// Softmax over axis p (rows) for each column q, in place.
// ---------------------------------------------------------------------------
__global__ void col_softmax(float* __restrict__ e)
{
    int b = blockIdx.y;
    int q = blockIdx.x * blockDim.x + threadIdx.x;   // 0..1023
    float* base = e + (size_t)b * PP * PP + q;

    float m = -INFINITY, s = 0.f;
    for (int p = 0; p < PP; p++) {
        float v  = base[(size_t)p * PP];
        float nm = fmaxf(m, v);
        s = s * __expf(m - nm) + __expf(v - nm);
        m = nm;
    }
    float inv = 1.f / s;
    for (int p = 0; p < PP; p++) {
        size_t off = (size_t)p * PP;
        base[off] = __expf(base[off] - m) * inv;
    }
}

// ---------------------------------------------------------------------------
// Row LayerNorm over 5120 + ReLU, in place. One block per row.
// ---------------------------------------------------------------------------
__global__ __launch_bounds__(256)
void ln_relu(float* __restrict__ y, const float* __restrict__ gg,
             const float* __restrict__ bb)
{
    long row = blockIdx.x;
    float* p = y + row * DOUT;
    int tid = threadIdx.x;

    float v[20];
    float s = 0.f;
    #pragma unroll
    for (int j = 0; j < 20; j++) { v[j] = p[tid + j*256]; s += v[j]; }

    __shared__ float red[256];
    red[tid] = s; __syncthreads();
    #pragma unroll
    for (int st = 128; st; st >>= 1) {
        if (tid < st) red[tid] += red[tid + st];
        __syncthreads();
    }
    float mu = red[0] * (1.f / DOUT);
    __syncthreads();

    float qs = 0.f;
    #pragma unroll
    for (int j = 0; j < 20; j++) { float d = v[j] - mu; qs += d*d; }
    red[tid] = qs; __syncthreads();
    #pragma unroll
    for (int st = 128; st; st >>= 1) {
        if (tid < st) red[tid] += red[tid + st];
        __syncthreads();
    }
    float is = rsqrtf(red[0] * (1.f / DOUT) + 1e-5f);

    #pragma unroll
    for (int j = 0; j < 20; j++) {
        int o = tid + j*256;
        float x = (v[j] - mu) * is * gg[o] + bb[o];
        p[o] = fmaxf(x, 0.f);
    }
}

// ---------------------------------------------------------------------------
// Launch
// ---------------------------------------------------------------------------
extern "C" void kernel_launch(void* const* d_in, const int* in_sizes, int n_in,
                              void* d_out, int out_size)
{
    const float* f     = (const float*)d_in[0];   // [8,1024,64]
    const float* r     = (const float*)d_in[1];   // [8,1]
    const float* bas0  = (const float*)d_in[2];
    const float* bas1  = (const float*)d_in[3];
    const float* bas2  = (const float*)d_in[4];
    const float* bas3  = (const float*)d_in[5];
    const float* W1    = (const float*)d_in[6];
    const float* b1    = (const float*)d_in[7];
    const float* g1    = (const float*)d_in[8];
    const float* be1   = (const float*)d_in[9];
    const float* W2    = (const float*)d_in[10];
    const float* b2    = (const float*)d_in[11];
    const float* g2    = (const float*)d_in[12];
    const float* be2   = (const float*)d_in[13];
    const float* W3    = (const float*)d_in[14];
    const float* b3    = (const float*)d_in[15];
    const float* trans = (const float*)d_in[16];  // [8,64,5120]
    const float* Wl1   = (const float*)d_in[17];  // [5120,2560]
    const float* bl1   = (const float*)d_in[18];
    const float* ln_g  = (const float*)d_in[19];
    const float* ln_b  = (const float*)d_in[20];
    const float* Wl2   = (const float*)d_in[21];  // [5120,5120]
    const float* bl2   = (const float*)d_in[22];
    float* out = (float*)d_out;

    float *R, *kern, *qkv, *e, *z, *y;
    cudaGetSymbolAddress((void**)&R,    g_R);
    cudaGetSymbolAddress((void**)&kern, g_kern);
    cudaGetSymbolAddress((void**)&qkv,  g_qkv);
    cudaGetSymbolAddress((void**)&e,    g_e);
    cudaGetSymbolAddress((void**)&z,    g_z);
    cudaGetSymbolAddress((void**)&y,    g_y);

    // 1) radial MLPs -> R
    radial_kernel<<<96, 256>>>(r, W1, b1, g1, be1, W2, b2, g2, be2, W3, b3, R);

    // 2) kernels
    {
        long total = 3L * BB * FIN * TOTAL_K;
        build_kern<<<(unsigned)((total + 255) / 256), 256>>>(R, bas0, bas1, bas2, bas3, kern);
    }

    // 3) qkv[t,b] = features[b] @ kern[t,b]   (M=1024,N=2560,K=64)
    for (int t = 0; t < 3; t++) {
        dim3 grid(TOTAL_K/128, PP/128, BB);
        tmma<0,0><<<grid, 256>>>(f,
                                 kern + (long)t*BB*FIN*TOTAL_K,
                                 qkv  + (long)t*BB*PP*TOTAL_K,
                                 PP, TOTAL_K, FIN, FIN, TOTAL_K, TOTAL_K,
                                 (long)PP*FIN, (long)FIN*TOTAL_K, (long)PP*TOTAL_K,
                                 1.f, nullptr, 0);
    }

    const int K0[4] = {0, 160, 640, 1440};
    const int KG[4] = {160, 480, 800, 1120};

    // 4-6) per-degree attention, reusing one score buffer e[8,1024,1024]
    for (int g = 0; g < 4; g++) {
        // scores: e[b] = scale * Q_seg @ K_seg^T  (M=N=1024, K=KG[g], full tiles)
        {
            dim3 grid(PP/128, PP/128, BB);
            float scale = 1.0f / sqrtf((float)KG[g]);
            tmma<1,0><<<grid, 256>>>(qkv + 2L*BB*PP*TOTAL_K + K0[g],
                                     qkv + 1L*BB*PP*TOTAL_K + K0[g],
                                     e,
                                     PP, PP, KG[g], TOTAL_K, TOTAL_K, PP,
                                     (long)PP*TOTAL_K, (long)PP*TOTAL_K, (long)PP*PP,
                                     scale, nullptr, 0);
        }
        // softmax over p for each column q
        col_softmax<<<dim3(PP/256, BB), 256>>>(e);
        // z segment = alpha @ V_seg  (M=1024, N=KG[g], K=1024) — partial N tiles
        {
            dim3 grid((KG[g] + 127)/128, PP/128, BB);
            tmma<0,1><<<grid, 256>>>(e,
                                     qkv + K0[g],               // t=0 (v)
                                     z   + K0[g],
                                     PP, KG[g], PP, PP, TOTAL_K, TOTAL_K,
                                     (long)PP*PP, (long)PP*TOTAL_K, (long)PP*TOTAL_K,
                                     1.f, nullptr, 0);
        }
    }

    // 7) y = z @ Wl1^T + bl1   (M=8192, N=5120, K=2560)
    {
        dim3 grid(DOUT/128, (BB*PP)/128, 1);
        tmma<1,0><<<grid, 256>>>(z, Wl1, y,
                                 BB*PP, DOUT, TOTAL_K, TOTAL_K, TOTAL_K, DOUT,
                                 0, 0, 0, 1.f, bl1, 0);
    }

    // 8) LayerNorm + ReLU in place on y
    ln_relu<<<BB*PP, 256>>>(y, ln_g, ln_b);

    // 9) out = features @ transform + bl2   (per-b, M=1024, N=5120, K=64)
    {
        dim3 grid(DOUT/128, PP/128, BB);
        tmma<0,0><<<grid, 256>>>(f, trans, out,
                                 PP, DOUT, FIN, FIN, DOUT, DOUT,
                                 (long)PP*FIN, (long)FIN*DOUT, (long)PP*DOUT,
                                 1.f, bl2, 0);
    }

    // 10) out += y @ Wl2^T   (M=8192, N=5120, K=5120)
    {
        dim3 grid(DOUT/128, (BB*PP)/128, 1);
        tmma<1,0><<<grid, 256>>>(y, Wl2, out,
                                 BB*PP, DOUT, DOUT, DOUT, DOUT, DOUT,
                                 0, 0, 0, 1.f, nullptr, 1);
    }
}

// round 9
// speedup vs baseline: 1.2592x; 1.1766x over previous
#include <cuda_runtime.h>
#include <cuda_bf16.h>
#include <math.h>

// ---------------------------------------------------------------------------
// Problem constants
// ---------------------------------------------------------------------------
#define BB   8        // batch
#define PP   1024     // points
#define FIN  64
#define MM   160      // multiplicity
#define DOUT 5120
#define TOTAL_K 2560
#define MID  32
#define RWID 10240    // M*FIN

// ---------------------------------------------------------------------------
// Scratch (static device globals; no allocations allowed)
// ---------------------------------------------------------------------------
__device__ float g_R    [3*4*BB*RWID];                 // radial outputs  (3.75 MB)
__device__ float g_kernT[(size_t)3*BB*TOTAL_K*FIN];    // kernels^T       (15.7 MB)
__device__ float g_qkv  [(size_t)3*BB*PP*TOTAL_K];     // q/k/v           (252 MB)
__device__ float g_vT   [(size_t)BB*TOTAL_K*PP];       // v transposed    (84 MB)
__device__ float g_trT  [(size_t)BB*DOUT*FIN];         // transform^T     (10.5 MB)
__device__ float g_e    [(size_t)BB*PP*PP];            // attn scores     (33.5 MB)
__device__ float g_z    [(size_t)BB*PP*TOTAL_K];       // attn output     (84 MB)
__device__ float g_y    [(size_t)BB*PP*DOUT];          // post-Wl1        (168 MB)

// ---------------------------------------------------------------------------
// Kernel 1: stacked radial MLPs.  One block per (t,g,b) = 96 blocks.
// ---------------------------------------------------------------------------
__global__ void radial_kernel(const float* __restrict__ r,
                              const float* __restrict__ W1, const float* __restrict__ b1,
                              const float* __restrict__ g1, const float* __restrict__ be1,
                              const float* __restrict__ W2, const float* __restrict__ b2,
                              const float* __restrict__ g2, const float* __restrict__ be2,
                              const float* __restrict__ W3, const float* __restrict__ b3,
                              float* __restrict__ R)
{
    int id  = blockIdx.x;     // tg*8 + b
    int b   = id & 7;
    int tg  = id >> 3;        // t*4+g
    int tid = threadIdx.x;
    float rb = r[b];          // r is [B,1]

    __shared__ float h1[32], h2[32];

    if (tid < 32) {
        float v = rb * W1[tg*32 + tid] + b1[tg*32 + tid];
        float mu = v;
        #pragma unroll
        for (int o = 16; o; o >>= 1) mu += __shfl_xor_sync(0xffffffffu, mu, o);
        mu *= (1.f/32.f);
        float d = v - mu;
        float var = d*d;
        #pragma unroll
        for (int o = 16; o; o >>= 1) var += __shfl_xor_sync(0xffffffffu, var, o);
        var *= (1.f/32.f);
        float x = d * rsqrtf(var + 1e-5f) * g1[tg*32 + tid] + be1[tg*32 + tid];
        h1[tid] = fmaxf(x, 0.f);
    }
    __syncthreads();

    if (tid < 32) {
        float acc = b2[tg*32 + tid];
        const float* w = W2 + ((size_t)tg*32 + tid) * 32;
        #pragma unroll
        for (int i = 0; i < 32; i++) acc += h1[i] * w[i];
        float mu = acc;
        #pragma unroll
        for (int o = 16; o; o >>= 1) mu += __shfl_xor_sync(0xffffffffu, mu, o);
        mu *= (1.f/32.f);
        float d = acc - mu;
        float var = d*d;
        #pragma unroll
        for (int o = 16; o; o >>= 1) var += __shfl_xor_sync(0xffffffffu, var, o);
        var *= (1.f/32.f);
        float x = d * rsqrtf(var + 1e-5f) * g2[tg*32 + tid] + be2[tg*32 + tid];
        h2[tid] = fmaxf(x, 0.f);
    }
    __syncthreads();

    for (int o = tid; o < RWID; o += blockDim.x) {
        float acc = b3[(size_t)tg*RWID + o];
        const float* w = W3 + ((size_t)tg*RWID + o) * 32;
        #pragma unroll
        for (int i = 0; i < 32; i++) acc += h2[i] * w[i];
        R[(size_t)id*RWID + o] = acc;
    }
}

// ---------------------------------------------------------------------------
// Kernel 2: build kernT[t,b,ktot,i] (transposed kernel, NT-friendly):
//   flat = i*(M*dout)+kg ; mo = flat/(dout*64) ; j = (flat/64)%dout ; mi = flat%64
//   kernT = R[t,g,b, mo*64+mi] * basis_g[b, j]
// ---------------------------------------------------------------------------
__global__ void build_kernT(const float* __restrict__ R,
                            const float* __restrict__ bas0, const float* __restrict__ bas1,
                            const float* __restrict__ bas2, const float* __restrict__ bas3,
                            float* __restrict__ kernT)
{
    long idx = (long)blockIdx.x * blockDim.x + threadIdx.x;
    const long total = 3L * BB * TOTAL_K * FIN;
    if (idx >= total) return;

    int i = (int)(idx % FIN);
    long rem = idx / FIN;
    int ktot = (int)(rem % TOTAL_K);
    rem /= TOTAL_K;
    int b = (int)(rem % BB);
    int t = (int)(rem / BB);

    int g, k0, dout;
    const float* bas;
    if      (ktot < 160)  { g = 0; k0 = 0;    dout = 1; bas = bas0; }
    else if (ktot < 640)  { g = 1; k0 = 160;  dout = 3; bas = bas1; }
    else if (ktot < 1440) { g = 2; k0 = 640;  dout = 5; bas = bas2; }
    else                  { g = 3; k0 = 1440; dout = 7; bas = bas3; }

    int kg  = ktot - k0;
    int lin = i * (MM * dout) + kg;
    int mo  = lin / (dout * FIN);
    int j   = (lin / FIN) % dout;
    int mi  = lin % FIN;

    float v = R[((size_t)((t*4 + g)*BB + b))*RWID + mo*FIN + mi] * bas[b*dout + j];
    kernT[idx] = v;
}

// ---------------------------------------------------------------------------
// Batched 32x32 tiled transpose: in [b][R][C] -> out [b][C][R].
// R, C multiples of 32.  Block 32x8.
// ---------------------------------------------------------------------------
__global__ void transpose_bat(const float* __restrict__ in, float* __restrict__ out,
                              int R, int C, long sIn, long sOut)
{
    __shared__ float tile[32][33];
    const float* ip = in  + (long)blockIdx.z * sIn;
    float*       op = out + (long)blockIdx.z * sOut;

    int c0 = blockIdx.x * 32, r0 = blockIdx.y * 32;
    int tx = threadIdx.x, ty = threadIdx.y;

    #pragma unroll
    for (int i = 0; i < 32; i += 8)
        tile[ty + i][tx] = ip[(long)(r0 + ty + i)*C + c0 + tx];
    __syncthreads();
    #pragma unroll
    for (int i = 0; i < 32; i += 8)
        op[(long)(c0 + ty + i)*R + r0 + tx] = tile[tx][ty + i];
}

// ---------------------------------------------------------------------------
// 3xTF32 NT GEMM, cp.async 2-stage pipeline.
// 128x128x16 tile, 256 threads (8 warps 2Mx4N), warp = 64x32 via 4x4 m16n8k8.
// A [M][K] lda, B [N][K] ldb, both k-contiguous (16B-aligned rows).
// GUARD=1: B rows may exceed N (zero-filled); epilogue col-guarded.
// M%128==0, K%16==0 always.  C = (acc?C:0) + alpha*A.B^T + (bias?bias[n]:0)
// ---------------------------------------------------------------------------
#define KP 20            // smem row stride in floats (conflict-free fragments)
#define STG_F (128*KP)   // floats per stage

__device__ __forceinline__ unsigned f2tf(float x) {
    unsigned r;
    asm("cvt.rna.tf32.f32 %0, %1;" : "=r"(r) : "f"(x));
    return r;
}
__device__ __forceinline__ void split_tf32(float x, unsigned& hi, unsigned& lo) {
    hi = f2tf(x);
    lo = f2tf(x - __uint_as_float(hi));
}
__device__ __forceinline__ void mma_tf32(float c[4], const unsigned a[4],
                                         const unsigned b[2]) {
    asm volatile(
        "mma.sync.aligned.m16n8k8.row.col.f32.tf32.tf32.f32 "
        "{%0,%1,%2,%3}, {%4,%5,%6,%7}, {%8,%9}, {%0,%1,%2,%3};"
        : "+f"(c[0]), "+f"(c[1]), "+f"(c[2]), "+f"(c[3])
        : "r"(a[0]), "r"(a[1]), "r"(a[2]), "r"(a[3]), "r"(b[0]), "r"(b[1]));
}

template<int GUARD>
__global__ __launch_bounds__(256)
void ntmma(const float* __restrict__ A, const float* __restrict__ B,
           float* __restrict__ C,
           int M, int N, int K, int lda, int ldb, int ldc,
           long sA, long sB, long sC,
           float alpha, const float* __restrict__ bias, int acc)
{
    __shared__ __align__(16) float As[2*STG_F];
    __shared__ __align__(16) float Bs[2*STG_F];

    A += (long)blockIdx.z * sA;
    B += (long)blockIdx.z * sB;
    C += (long)blockIdx.z * sC;

    const int m0 = blockIdx.y * 128;
    const int n0 = blockIdx.x * 128;
    const int tid  = threadIdx.x;
    const int lane = tid & 31;
    const int warp = tid >> 5;
    const int wm = warp & 1;        // 0..1 (64-row group)
    const int wn = warp >> 1;       // 0..3 (32-col group)
    const int g  = lane >> 2;       // 0..7
    const int t  = lane & 3;        // 0..3

    const unsigned aBase = (unsigned)__cvta_generic_to_shared(As);
    const unsigned bBase = (unsigned)__cvta_generic_to_shared(Bs);

    // per-thread copy coordinates: 512 16B-chunks per tile, 2 per thread
    const int mr0 = tid >> 2,           kq0 = (tid & 3) * 4;
    const int mr1 = (tid + 256) >> 2,   kq1 = ((tid + 256) & 3) * 4;

    float c[4][4][4];
    #pragma unroll
    for (int i = 0; i < 4; i++)
        #pragma unroll
        for (int j = 0; j < 4; j++)
            #pragma unroll
            for (int k = 0; k < 4; k++) c[i][j][k] = 0.f;

    auto copy_stage = [&](int s, int ko) {
        unsigned so = (unsigned)s * (STG_F * 4);
        // chunk 0
        {
            unsigned off = so + (mr0*KP + kq0)*4;
            const float* ga = A + (long)(m0 + mr0)*lda + ko + kq0;
            asm volatile("cp.async.cg.shared.global [%0], [%1], 16;"
                         :: "r"(aBase + off), "l"(ga));
            int nr = n0 + mr0, sz = 16;
            if (GUARD && nr >= N) { sz = 0; nr = 0; }
            const float* gb = B + (long)nr*ldb + ko + kq0;
            asm volatile("cp.async.cg.shared.global [%0], [%1], 16, %2;"
                         :: "r"(bBase + off), "l"(gb), "r"(sz));
        }
        // chunk 1
        {
            unsigned off = so + (mr1*KP + kq1)*4;
            const float* ga = A + (long)(m0 + mr1)*lda + ko + kq1;
            asm volatile("cp.async.cg.shared.global [%0], [%1], 16;"
                         :: "r"(aBase + off), "l"(ga));
            int nr = n0 + mr1, sz = 16;
            if (GUARD && nr >= N) { sz = 0; nr = 0; }
            const float* gb = B + (long)nr*ldb + ko + kq1;
            asm volatile("cp.async.cg.shared.global [%0], [%1], 16, %2;"
                         :: "r"(bBase + off), "l"(gb), "r"(sz));
        }
    };

    const int KT = K / 16;
    copy_stage(0, 0);
    asm volatile("cp.async.commit_group;");

    for (int kt = 0; kt < KT; kt++) {
        asm volatile("cp.async.wait_group 0;");
        __syncthreads();
        if (kt + 1 < KT) {
            copy_stage((kt + 1) & 1, (kt + 1) * 16);
            asm volatile("cp.async.commit_group;");
        }
        const float* as = As + (kt & 1) * STG_F;
        const float* bs = Bs + (kt & 1) * STG_F;

        #pragma unroll
        for (int ks = 0; ks < 16; ks += 8) {
            unsigned aH[4][4], aL[4][4], bH[4][2], bL[4][2];
            #pragma unroll
            for (int mt = 0; mt < 4; mt++) {
                int am = wm*64 + mt*16;
                float r0 = as[(am + g    )*KP + ks + t    ];
                float r1 = as[(am + g + 8)*KP + ks + t    ];
                float r2 = as[(am + g    )*KP + ks + t + 4];
                float r3 = as[(am + g + 8)*KP + ks + t + 4];
                split_tf32(r0, aH[mt][0], aL[mt][0]);
                split_tf32(r1, aH[mt][1], aL[mt][1]);
                split_tf32(r2, aH[mt][2], aL[mt][2]);
                split_tf32(r3, aH[mt][3], aL[mt][3]);
            }
            #pragma unroll
            for (int nt = 0; nt < 4; nt++) {
                int bn = wn*32 + nt*8;
                float s0 = bs[(bn + g)*KP + ks + t    ];
                float s1 = bs[(bn + g)*KP + ks + t + 4];
                split_tf32(s0, bH[nt][0], bL[nt][0]);
                split_tf32(s1, bH[nt][1], bL[nt][1]);
            }
            #pragma unroll
            for (int mt = 0; mt < 4; mt++)
                #pragma unroll
                for (int nt = 0; nt < 4; nt++) {
                    mma_tf32(c[mt][nt], aH[mt], bL[nt]);
                    mma_tf32(c[mt][nt], aL[mt], bH[nt]);
                    mma_tf32(c[mt][nt], aH[mt], bH[nt]);
                }
        }
        // no trailing sync: next iteration's wait+sync protects buffer reuse
    }

    // ---- epilogue ----
    #pragma unroll
    for (int mt = 0; mt < 4; mt++) {
        #pragma unroll
        for (int nt = 0; nt < 4; nt++) {
            int col = n0 + wn*32 + nt*8 + t*2;
            if (GUARD && col >= N) continue;   // N even, col even -> pair safe
            #pragma unroll
            for (int h = 0; h < 2; h++) {
                int row = m0 + wm*64 + mt*16 + g + h*8;
                float v0 = c[mt][nt][h*2 + 0] * alpha;
                float v1 = c[mt][nt][h*2 + 1] * alpha;
                long off = (long)row*ldc + col;
                if (bias) { v0 += bias[col]; v1 += bias[col + 1]; }
                if (acc) {
                    float2 c2 = *(const float2*)&C[off];
                    v0 += c2.x; v1 += c2.y;
                }
                float2 o2; o2.x = v0; o2.y = v1;
                *(float2*)&C[off] = o2;
            }
        }
    }
}

// ---------------------------------------------------------------------------
// Softmax over axis p (rows) for each column q, in place.
// ---------------------------------------------------------------------------
__global__ void col_softmax(float* __restrict__ e)
{
    int b = blockIdx.y;
    int q = blockIdx.x * blockDim.x + threadIdx.x;   // 0..1023
    float* base = e + (size_t)b * PP * PP + q;

    float m = -INFINITY, s = 0.f;
    for (int p = 0; p < PP; p++) {
        float v  = base[(size_t)p * PP];
        float nm = fmaxf(m, v);
        s = s * __expf(m - nm) + __expf(v - nm);
        m = nm;
    }
    float inv = 1.f / s;
    for (int p = 0; p < PP; p++) {
        size_t off = (size_t)p * PP;
        base[off] = __expf(base[off] - m) * inv;
    }
}

// ---------------------------------------------------------------------------
// Row LayerNorm over 5120 + ReLU, in place. One block per row.
// ---------------------------------------------------------------------------
__global__ __launch_bounds__(256)
void ln_relu(float* __restrict__ y, const float* __restrict__ gg,
             const float* __restrict__ bb)
{
    long row = blockIdx.x;
    float* p = y + row * DOUT;
    int tid = threadIdx.x;

    float v[20];
    float s = 0.f;
    #pragma unroll
    for (int j = 0; j < 20; j++) { v[j] = p[tid + j*256]; s += v[j]; }

    __shared__ float red[256];
    red[tid] = s; __syncthreads();
    #pragma unroll
    for (int st = 128; st; st >>= 1) {
        if (tid < st) red[tid] += red[tid + st];
        __syncthreads();
    }
    float mu = red[0] * (1.f / DOUT);
    __syncthreads();

    float qs = 0.f;
    #pragma unroll
    for (int j = 0; j < 20; j++) { float d = v[j] - mu; qs += d*d; }
    red[tid] = qs; __syncthreads();
    #pragma unroll
    for (int st = 128; st; st >>= 1) {
        if (tid < st) red[tid] += red[tid + st];
        __syncthreads();
    }
    float is = rsqrtf(red[0] * (1.f / DOUT) + 1e-5f);

    #pragma unroll
    for (int j = 0; j < 20; j++) {
        int o = tid + j*256;
        float x = (v[j] - mu) * is * gg[o] + bb[o];
        p[o] = fmaxf(x, 0.f);
    }
}

// ---------------------------------------------------------------------------
// Launch
// ---------------------------------------------------------------------------
extern "C" void kernel_launch(void* const* d_in, const int* in_sizes, int n_in,
                              void* d_out, int out_size)
{
    const float* f     = (const float*)d_in[0];   // [8,1024,64]
    const float* r     = (const float*)d_in[1];   // [8,1]
    const float* bas0  = (const float*)d_in[2];
    const float* bas1  = (const float*)d_in[3];
    const float* bas2  = (const float*)d_in[4];
    const float* bas3  = (const float*)d_in[5];
    const float* W1    = (const float*)d_in[6];
    const float* b1    = (const float*)d_in[7];
    const float* g1    = (const float*)d_in[8];
    const float* be1   = (const float*)d_in[9];
    const float* W2    = (const float*)d_in[10];
    const float* b2    = (const float*)d_in[11];
    const float* g2    = (const float*)d_in[12];
    const float* be2   = (const float*)d_in[13];
    const float* W3    = (const float*)d_in[14];
    const float* b3    = (const float*)d_in[15];
    const float* trans = (const float*)d_in[16];  // [8,64,5120]
    const float* Wl1   = (const float*)d_in[17];  // [5120,2560]
    const float* bl1   = (const float*)d_in[18];
    const float* ln_g  = (const float*)d_in[19];
    const float* ln_b  = (const float*)d_in[20];
    const float* Wl2   = (const float*)d_in[21];  // [5120,5120]
    const float* bl2   = (const float*)d_in[22];
    float* out = (float*)d_out;

    float *R, *kernT, *qkv, *vT, *trT, *e, *z, *y;
    cudaGetSymbolAddress((void**)&R,     g_R);
    cudaGetSymbolAddress((void**)&kernT, g_kernT);
    cudaGetSymbolAddress((void**)&qkv,   g_qkv);
    cudaGetSymbolAddress((void**)&vT,    g_vT);
    cudaGetSymbolAddress((void**)&trT,   g_trT);
    cudaGetSymbolAddress((void**)&e,     g_e);
    cudaGetSymbolAddress((void**)&z,     g_z);
    cudaGetSymbolAddress((void**)&y,     g_y);

    // 1) radial MLPs -> R
    radial_kernel<<<96, 256>>>(r, W1, b1, g1, be1, W2, b2, g2, be2, W3, b3, R);

    // 2) kernels (transposed: [t,b,ktot,i])
    {
        long total = 3L * BB * TOTAL_K * FIN;
        build_kernT<<<(unsigned)((total + 255) / 256), 256>>>(R, bas0, bas1, bas2, bas3, kernT);
    }

    // 3) qkv[t,b] = f[b] @ kernT[t,b]^T   (NT: M=1024, N=2560, K=64)
    for (int t = 0; t < 3; t++) {
        dim3 grid(TOTAL_K/128, PP/128, BB);
        ntmma<0><<<grid, 256>>>(f,
                                kernT + (long)t*BB*TOTAL_K*FIN,
                                qkv   + (long)t*BB*PP*TOTAL_K,
                                PP, TOTAL_K, FIN, FIN, FIN, TOTAL_K,
                                (long)PP*FIN, (long)TOTAL_K*FIN, (long)PP*TOTAL_K,
                                1.f, nullptr, 0);
    }

    // 4) transpose v -> vT  ([b,1024,2560] -> [b,2560,1024])
    transpose_bat<<<dim3(TOTAL_K/32, PP/32, BB), dim3(32, 8)>>>(
        qkv, vT, PP, TOTAL_K, (long)PP*TOTAL_K, (long)TOTAL_K*PP);

    // 5) transpose transform -> trT  ([b,64,5120] -> [b,5120,64])
    transpose_bat<<<dim3(DOUT/32, FIN/32, BB), dim3(32, 8)>>>(
        trans, trT, FIN, DOUT, (long)FIN*DOUT, (long)DOUT*FIN);

    const int K0[4] = {0, 160, 640, 1440};
    const int KG[4] = {160, 480, 800, 1120};

    // 6) per-degree attention, reusing one score buffer e[8,1024,1024]
    for (int g = 0; g < 4; g++) {
        // scores: e[b] = scale * Q_seg @ K_seg^T  (NT, full tiles, K=KG[g])
        {
            dim3 grid(PP/128, PP/128, BB);
            float scale = 1.0f / sqrtf((float)KG[g]);
            ntmma<0><<<grid, 256>>>(qkv + 2L*BB*PP*TOTAL_K + K0[g],
                                    qkv + 1L*BB*PP*TOTAL_K + K0[g],
                                    e,
                                    PP, PP, KG[g], TOTAL_K, TOTAL_K, PP,
                                    (long)PP*TOTAL_K, (long)PP*TOTAL_K, (long)PP*PP,
                                    scale, nullptr, 0);
        }
        // softmax over p for each column q
        col_softmax<<<dim3(PP/256, BB), 256>>>(e);
        // z segment = alpha @ vT_seg^T  (NT, M=1024, N=KG[g] guarded, K=1024)
        {
            dim3 grid((KG[g] + 127)/128, PP/128, BB);
            ntmma<1><<<grid, 256>>>(e,
                                    vT + (long)K0[g]*PP,
                                    z  + K0[g],
                                    PP, KG[g], PP, PP, PP, TOTAL_K,
                                    (long)PP*PP, (long)TOTAL_K*PP, (long)PP*TOTAL_K,
                                    1.f, nullptr, 0);
        }
    }

    // 7) y = z @ Wl1^T + bl1   (NT: M=8192, N=5120, K=2560)
    {
        dim3 grid(DOUT/128, (BB*PP)/128, 1);
        ntmma<0><<<grid, 256>>>(z, Wl1, y,
                                BB*PP, DOUT, TOTAL_K, TOTAL_K, TOTAL_K, DOUT,
                                0, 0, 0, 1.f, bl1, 0);
    }

    // 8) LayerNorm + ReLU in place on y
    ln_relu<<<BB*PP, 256>>>(y, ln_g, ln_b);

    // 9) out = f @ trT^T + bl2   (NT per-b: M=1024, N=5120, K=64)
    {
        dim3 grid(DOUT/128, PP/128, BB);
        ntmma<0><<<grid, 256>>>(f, trT, out,
                                PP, DOUT, FIN, FIN, FIN, DOUT,
                                (long)PP*FIN, (long)DOUT*FIN, (long)PP*DOUT,
                                1.f, bl2, 0);
    }

    // 10) out += y @ Wl2^T   (NT: M=8192, N=5120, K=5120)
    {
        dim3 grid(DOUT/128, (BB*PP)/128, 1);
        ntmma<0><<<grid, 256>>>(y, Wl2, out,
                                BB*PP, DOUT, DOUT, DOUT, DOUT, DOUT,
                                0, 0, 0, 1.f, nullptr, 1);
    }
}